// round 8
// baseline (speedup 1.0000x reference)
#include <cuda_runtime.h>
#include <cuda_bf16.h>
#include <math.h>
#include <stdint.h>

// ---------------- problem constants ----------------
#define KK 5
#define BB 32
#define TT 64
#define DIN 4096
#define HH 256            // GRU hidden
#define H2 512            // 2*H
#define NSEQ 192          // 160 S-sequences + 32 Q-sequences
#define NS 160            // K*B
#define MTOT 12288        // NSEQ*TT rows
#define NTOT 1536         // 3H fwd | 3H bwd
#define ATTN_SMEM ((64*65*3 + 64*520)*4)

#define AELEMS ((size_t)MTOT * DIN)
#define BELEMS ((size_t)NTOT * DIN)
#define FAEL   ((size_t)NS * TT * H2)      // F_S elements (10240 x 512)
#define WAEL   ((size_t)H2 * H2)           // W_attn elements

// mma-GEMM tiling: plain bf16 GEMM over K' = 3*K (split planes folded into K)
#define BKC 64
#define NCHUNK (3 * DIN / BKC)       // 192
#define TILE_B (128 * 144)           // 18432 B: 128 rows x (64+8 pad) bf16
#define STAGE_B (2 * TILE_B)         // A tile + B tile = 36864
#define STAGES 3
#define GMM_SMEM (STAGES * STAGE_B)  // 110592 (2 CTAs/SM)
#define NCHUNK2 (3 * H2 / BKC)       // 24 (keys gemm)

// ---------------- scratch (device globals; no allocation allowed) ----------------
__device__ float g_XP[(size_t)NSEQ * TT * NTOT];   // input projections, fwd|bwd gates
__device__ float g_F [(size_t)NSEQ * TT * H2];     // BiGRU features [n][t][fwd256|bwd256]
__device__ float g_keys[(size_t)NS * TT * H2];     // W_attn(F_S)+bias
__device__ float g_diff[(size_t)NS * TT * 2];      // (cos, euc) dml inputs
__device__ __nv_bfloat16 g_Abf[2 * AELEMS];        // bf16 hi|lo planes of inputs
__device__ __nv_bfloat16 g_Bbf[2 * BELEMS];        // bf16 hi|lo planes of Wih_f|Wih_b
__device__ __nv_bfloat16 g_Fbf[2 * FAEL];          // bf16 hi|lo planes of F_S
__device__ __nv_bfloat16 g_Wabf[2 * WAEL];         // bf16 hi|lo planes of W_attn

__device__ __forceinline__ float sigm(float x) { return 1.f / (1.f + expf(-x)); }

__device__ __forceinline__ uint32_t smem_u32(const void* p) {
    uint32_t a;
    asm("{ .reg .u64 t; cvta.to.shared.u64 t, %1; cvt.u32.u64 %0, t; }" : "=r"(a) : "l"(p));
    return a;
}
__device__ __forceinline__ void ldsm4(uint32_t* r, uint32_t a) {
    asm volatile("ldmatrix.sync.aligned.m8n8.x4.shared.b16 {%0,%1,%2,%3}, [%4];"
        : "=r"(r[0]), "=r"(r[1]), "=r"(r[2]), "=r"(r[3]) : "r"(a));
}
__device__ __forceinline__ void mma_bf16(float* c, const uint32_t* a, uint32_t b0, uint32_t b1) {
    asm volatile("mma.sync.aligned.m16n8k16.row.col.f32.bf16.bf16.f32 "
        "{%0,%1,%2,%3}, {%4,%5,%6,%7}, {%8,%9}, {%0,%1,%2,%3};"
        : "+f"(c[0]), "+f"(c[1]), "+f"(c[2]), "+f"(c[3])
        : "r"(a[0]), "r"(a[1]), "r"(a[2]), "r"(a[3]), "r"(b0), "r"(b1));
}
__device__ __forceinline__ void cpasync16(uint32_t s, const void* g) {
    asm volatile("cp.async.cg.shared.global [%0], [%1], 16;" :: "r"(s), "l"(g));
}
#define CP_COMMIT() asm volatile("cp.async.commit_group;" ::: "memory")

// packed f32x2 fma
__device__ __forceinline__ void ffma2(uint64_t& acc, uint64_t a, uint64_t b) {
    asm("fma.rn.f32x2 %0, %1, %2, %0;" : "+l"(acc) : "l"(a), "l"(b));
}
__device__ __forceinline__ float upk_sum(uint64_t v) {
    float x, y;
    asm("mov.b64 {%0,%1}, %2;" : "=f"(x), "=f"(y) : "l"(v));
    return x + y;
}

// ---------------- fp32 -> bf16 hi/lo split ----------------
__global__ void __launch_bounds__(256) convert_split(
    const float* __restrict__ src, __nv_bfloat16* __restrict__ hi, __nv_bfloat16* __restrict__ lo)
{
    size_t i = ((size_t)blockIdx.x * 256 + threadIdx.x) * 4;
    float4 v = *(const float4*)(src + i);
    float vv[4] = { v.x, v.y, v.z, v.w };
    union { __nv_bfloat16 b[4]; uint2 u; } H, L;
#pragma unroll
    for (int j = 0; j < 4; j++) {
        H.b[j] = __float2bfloat16(vv[j]);
        L.b[j] = __float2bfloat16(vv[j] - __bfloat162float(H.b[j]));
    }
    *(uint2*)(hi + i) = H.u;
    *(uint2*)(lo + i) = L.u;
}

// both weight matrices in ONE launch (keeps gemm_mma at launch slot #4 for ncu)
__global__ void __launch_bounds__(256) convert_w(
    const float* __restrict__ wf, const float* __restrict__ wb,
    __nv_bfloat16* __restrict__ hi, __nv_bfloat16* __restrict__ lo)
{
    int bb = blockIdx.x;
    const float* src = wf;
    size_t off = 0;
    if (bb >= 3072) { src = wb; off = (size_t)768 * DIN; bb -= 3072; }
    size_t i = ((size_t)bb * 256 + threadIdx.x) * 4;
    float4 v = *(const float4*)(src + i);
    float vv[4] = { v.x, v.y, v.z, v.w };
    union { __nv_bfloat16 b[4]; uint2 u; } H, L;
#pragma unroll
    for (int j = 0; j < 4; j++) {
        H.b[j] = __float2bfloat16(vv[j]);
        L.b[j] = __float2bfloat16(vv[j] - __bfloat162float(H.b[j]));
    }
    *(uint2*)(hi + off + i) = H.u;
    *(uint2*)(lo + off + i) = L.u;
}

// ---------------- bf16 GEMM via mma.sync, K'=12288, BK=64, 3-stage cp.async ----------------
// grid (12 N-tiles fastest, 96 M-tiles), 256 threads, tile 128x128.
// Fragment double-buffering: ldsm for kh+1 issued before mma of kh.
__global__ void __launch_bounds__(256, 2) gemm_mma(
    const float* __restrict__ bias1, const float* __restrict__ bias2)
{
    extern __shared__ __align__(128) char smem[];
    uint32_t sbase = smem_u32(smem);
    int tid = threadIdx.x;
    int wid = tid >> 5, lane = tid & 31;
    int warp_m = wid & 1, warp_n = wid >> 1;
    int bn = blockIdx.x * 128, bm = blockIdx.y * 128;

    float acc[4][4][4];
#pragma unroll
    for (int i = 0; i < 4; i++)
#pragma unroll
        for (int j = 0; j < 4; j++)
#pragma unroll
            for (int c = 0; c < 4; c++) acc[i][j][c] = 0.f;

    // per-warp ldsm base addresses (kh-invariant parts)
    int arow = warp_m * 64 + (lane & 7) + ((lane >> 3) & 1) * 8;
    uint32_t aoff = arow * 144 + ((lane >> 4) & 1) * 16;
    int brow = warp_n * 32 + ((lane >> 4) & 1) * 8 + (lane & 7);
    uint32_t boff = TILE_B + brow * 144 + ((lane >> 3) & 1) * 16;

    auto load_stage = [&](int ci, int s) {
        int p = ci % 3;                 // plane phase: 0 Ah*Bh, 1 Ah*Bl, 2 Al*Bh
        int k0 = (ci / 3) * BKC;
        const __nv_bfloat16* Ap = g_Abf + (p == 2 ? AELEMS : 0);
        const __nv_bfloat16* Bp = g_Bbf + (p == 1 ? BELEMS : 0);
        uint32_t sb_s = sbase + s * STAGE_B;
#pragma unroll
        for (int l = 0; l < 8; l++) {
            int idx = tid + l * 256;          // 0..2047
            int isB = idx >> 10;
            int r = (idx >> 3) & 127;
            int seg = idx & 7;
            uint32_t sa = sb_s + isB * TILE_B + r * 144 + seg * 16;
            const __nv_bfloat16* gp = isB
                ? Bp + (size_t)(bn + r) * DIN + k0 + seg * 8
                : Ap + (size_t)(bm + r) * DIN + k0 + seg * 8;
            cpasync16(sa, gp);
        }
        CP_COMMIT();
    };

    auto ldfrags = [&](uint32_t base, int kh, uint32_t* af, uint32_t* bfr) {
#pragma unroll
        for (int mf = 0; mf < 4; mf++)
            ldsm4(&af[mf * 4], base + aoff + mf * 16 * 144 + kh * 32);
#pragma unroll
        for (int nf2 = 0; nf2 < 2; nf2++)
            ldsm4(&bfr[nf2 * 4], base + boff + nf2 * 16 * 144 + kh * 32);
    };

    auto compute_stage = [&](int s) {
        uint32_t base = sbase + s * STAGE_B;
        uint32_t af[2][16], bfr[2][8];
        ldfrags(base, 0, af[0], bfr[0]);
#pragma unroll
        for (int kh = 0; kh < 4; kh++) {
            int cur = kh & 1, nxt = cur ^ 1;
            if (kh < 3) ldfrags(base, kh + 1, af[nxt], bfr[nxt]);
#pragma unroll
            for (int mf = 0; mf < 4; mf++)
#pragma unroll
                for (int nf = 0; nf < 4; nf++) {
                    int bi = (nf >> 1) * 4 + (nf & 1) * 2;
                    mma_bf16(acc[mf][nf], &af[cur][mf * 4], bfr[cur][bi], bfr[cur][bi + 1]);
                }
        }
    };

    load_stage(0, 0);
    load_stage(1, 1);

#pragma unroll 1
    for (int ci = 0; ci < NCHUNK; ci++) {
        if (ci < NCHUNK - 1) asm volatile("cp.async.wait_group 1;" ::: "memory");
        else                 asm volatile("cp.async.wait_group 0;" ::: "memory");
        __syncthreads();
        if (ci + 2 < NCHUNK) load_stage(ci + 2, (ci + 2) % STAGES);
        compute_stage(ci % STAGES);
    }

    // epilogue: add bias, write fp32
    float bcol[4][2];
#pragma unroll
    for (int nf = 0; nf < 4; nf++) {
        int col = bn + warp_n * 32 + nf * 8 + (lane & 3) * 2;
        bcol[nf][0] = (col < 768) ? bias1[col] : bias2[col - 768];
        bcol[nf][1] = (col + 1 < 768) ? bias1[col + 1] : bias2[col + 1 - 768];
    }
#pragma unroll
    for (int mf = 0; mf < 4; mf++) {
        int m = bm + warp_m * 64 + mf * 16 + (lane >> 2);
#pragma unroll
        for (int nf = 0; nf < 4; nf++) {
            size_t o = (size_t)m * NTOT + bn + warp_n * 32 + nf * 8 + (lane & 3) * 2;
            float2 v0 = { acc[mf][nf][0] + bcol[nf][0], acc[mf][nf][1] + bcol[nf][1] };
            *(float2*)(g_XP + o) = v0;
            float2 v1 = { acc[mf][nf][2] + bcol[nf][0], acc[mf][nf][3] + bcol[nf][1] };
            *(float2*)(g_XP + o + (size_t)8 * NTOT) = v1;
        }
    }
}

// ---------------- keys GEMM via bf16 mma: g_keys = F_S @ W_attn^T + bias ----------------
// K'=3*512, grid (4 N-tiles, 80 M-tiles).
__global__ void __launch_bounds__(256, 2) gemm_keys_mma(const float* __restrict__ bias1)
{
    extern __shared__ __align__(128) char smem[];
    uint32_t sbase = smem_u32(smem);
    int tid = threadIdx.x;
    int wid = tid >> 5, lane = tid & 31;
    int warp_m = wid & 1, warp_n = wid >> 1;
    int bn = blockIdx.x * 128, bm = blockIdx.y * 128;

    float acc[4][4][4];
#pragma unroll
    for (int i = 0; i < 4; i++)
#pragma unroll
        for (int j = 0; j < 4; j++)
#pragma unroll
            for (int c = 0; c < 4; c++) acc[i][j][c] = 0.f;

    int arow = warp_m * 64 + (lane & 7) + ((lane >> 3) & 1) * 8;
    uint32_t aoff = arow * 144 + ((lane >> 4) & 1) * 16;
    int brow = warp_n * 32 + ((lane >> 4) & 1) * 8 + (lane & 7);
    uint32_t boff = TILE_B + brow * 144 + ((lane >> 3) & 1) * 16;

    auto load_stage = [&](int ci, int s) {
        int p = ci % 3;
        int k0 = (ci / 3) * BKC;
        const __nv_bfloat16* Ap = g_Fbf + (p == 2 ? FAEL : 0);
        const __nv_bfloat16* Bp = g_Wabf + (p == 1 ? WAEL : 0);
        uint32_t sb_s = sbase + s * STAGE_B;
#pragma unroll
        for (int l = 0; l < 8; l++) {
            int idx = tid + l * 256;
            int isB = idx >> 10;
            int r = (idx >> 3) & 127;
            int seg = idx & 7;
            uint32_t sa = sb_s + isB * TILE_B + r * 144 + seg * 16;
            const __nv_bfloat16* gp = isB
                ? Bp + (size_t)(bn + r) * H2 + k0 + seg * 8
                : Ap + (size_t)(bm + r) * H2 + k0 + seg * 8;
            cpasync16(sa, gp);
        }
        CP_COMMIT();
    };

    auto ldfrags = [&](uint32_t base, int kh, uint32_t* af, uint32_t* bfr) {
#pragma unroll
        for (int mf = 0; mf < 4; mf++)
            ldsm4(&af[mf * 4], base + aoff + mf * 16 * 144 + kh * 32);
#pragma unroll
        for (int nf2 = 0; nf2 < 2; nf2++)
            ldsm4(&bfr[nf2 * 4], base + boff + nf2 * 16 * 144 + kh * 32);
    };

    auto compute_stage = [&](int s) {
        uint32_t base = sbase + s * STAGE_B;
        uint32_t af[2][16], bfr[2][8];
        ldfrags(base, 0, af[0], bfr[0]);
#pragma unroll
        for (int kh = 0; kh < 4; kh++) {
            int cur = kh & 1, nxt = cur ^ 1;
            if (kh < 3) ldfrags(base, kh + 1, af[nxt], bfr[nxt]);
#pragma unroll
            for (int mf = 0; mf < 4; mf++)
#pragma unroll
                for (int nf = 0; nf < 4; nf++) {
                    int bi = (nf >> 1) * 4 + (nf & 1) * 2;
                    mma_bf16(acc[mf][nf], &af[cur][mf * 4], bfr[cur][bi], bfr[cur][bi + 1]);
                }
        }
    };

    load_stage(0, 0);
    load_stage(1, 1);

#pragma unroll 1
    for (int ci = 0; ci < NCHUNK2; ci++) {
        if (ci < NCHUNK2 - 1) asm volatile("cp.async.wait_group 1;" ::: "memory");
        else                  asm volatile("cp.async.wait_group 0;" ::: "memory");
        __syncthreads();
        if (ci + 2 < NCHUNK2) load_stage(ci + 2, (ci + 2) % STAGES);
        compute_stage(ci % STAGES);
    }

    float bcol[4][2];
#pragma unroll
    for (int nf = 0; nf < 4; nf++) {
        int col = bn + warp_n * 32 + nf * 8 + (lane & 3) * 2;
        bcol[nf][0] = bias1[col];
        bcol[nf][1] = bias1[col + 1];
    }
#pragma unroll
    for (int mf = 0; mf < 4; mf++) {
        int m = bm + warp_m * 64 + mf * 16 + (lane >> 2);
#pragma unroll
        for (int nf = 0; nf < 4; nf++) {
            size_t o = (size_t)m * H2 + bn + warp_n * 32 + nf * 8 + (lane & 3) * 2;
            float2 v0 = { acc[mf][nf][0] + bcol[nf][0], acc[mf][nf][1] + bcol[nf][1] };
            *(float2*)(g_keys + o) = v0;
            float2 v1 = { acc[mf][nf][2] + bcol[nf][0], acc[mf][nf][3] + bcol[nf][1] };
            *(float2*)(g_keys + o + (size_t)8 * H2) = v1;
        }
    }
}

// ---------------- GRU recurrent scan: 64 blocks = 32 seq-groups x 2 directions, 6 seqs ----------------
__global__ void __launch_bounds__(256) bigru_scan(
    const float* __restrict__ Whh_f, const float* __restrict__ bhh_f,
    const float* __restrict__ Whh_b, const float* __restrict__ bhh_b)
{
    __shared__ __align__(16) float sh[6][256];
    int tid = threadIdx.x;
    int d = blockIdx.x & 1;
    int nb = (blockIdx.x >> 1) * 6;

#pragma unroll
    for (int s = 0; s < 6; s++) sh[s][tid] = 0.f;
    __syncthreads();

    const float* W  = d ? Whh_b : Whh_f;
    const float* BH = d ? bhh_b : bhh_f;
    float bh_r = BH[tid], bh_z = BH[256 + tid], bh_n = BH[512 + tid];
    const float* wr = W + (size_t)tid * 256;
    const float* wz = W + (size_t)(256 + tid) * 256;
    const float* wn = W + (size_t)(512 + tid) * 256;

    for (int t = 0; t < 64; t++) {
        int tt = d ? (63 - t) : t;
        uint64_t ar[6] = {0,0,0,0,0,0}, az[6] = {0,0,0,0,0,0}, an[6] = {0,0,0,0,0,0};
        for (int i = 0; i < 256; i += 4) {
            ulonglong2 r2 = *(const ulonglong2*)(wr + i);
            ulonglong2 z2 = *(const ulonglong2*)(wz + i);
            ulonglong2 n2 = *(const ulonglong2*)(wn + i);
#pragma unroll
            for (int s = 0; s < 6; s++) {
                ulonglong2 h2 = *(const ulonglong2*)(&sh[s][i]);
                ffma2(ar[s], r2.x, h2.x); ffma2(ar[s], r2.y, h2.y);
                ffma2(az[s], z2.x, h2.x); ffma2(az[s], z2.y, h2.y);
                ffma2(an[s], n2.x, h2.x); ffma2(an[s], n2.y, h2.y);
            }
        }
        float hn[6];
#pragma unroll
        for (int s = 0; s < 6; s++) {
            int n = nb + s;
            const float* xp = g_XP + ((size_t)n * 64 + tt) * NTOT + d * 768;
            float r  = sigm(xp[tid]       + upk_sum(ar[s]) + bh_r);
            float z  = sigm(xp[256 + tid] + upk_sum(az[s]) + bh_z);
            float ng = tanhf(xp[512 + tid] + r * (upk_sum(an[s]) + bh_n));
            hn[s] = (1.f - z) * ng + z * sh[s][tid];
        }
        __syncthreads();
#pragma unroll
        for (int s = 0; s < 6; s++) {
            sh[s][tid] = hn[s];
            g_F[((size_t)(nb + s) * 64 + tt) * 512 + d * 256 + tid] = hn[s];
        }
        __syncthreads();
    }
}

// ---------------- attention + softmax + Hc + cos/euc, one block per (k,b) ----------------
__global__ void __launch_bounds__(256) attn_kernel(
    const int* __restrict__ s_ln_arr, const int* __restrict__ q_ln_arr,
    float* __restrict__ d_out)
{
    extern __shared__ float sm[];
    float* ssc = sm;                 // [64][65] scores -> A
    float* sk  = sm + 64 * 65;       // [64][65] keys tile
    float* sq  = sk + 64 * 65;       // [64][65] F_Q tile
    float* shc = sq + 64 * 65;       // [64][520] Hc

    int kb = blockIdx.x;
    int b = kb & 31;
    int tid = threadIdx.x;
    int q_ln = q_ln_arr[b];
    int s_ln = s_ln_arr[kb];

    const float* keys = g_keys + (size_t)kb * 64 * 512;
    const float* FQ   = g_F + ((size_t)(160 + b) * 64) * 512;
    const float* FS   = g_F + ((size_t)kb * 64) * 512;

    int tx = tid & 15, ty = tid >> 4;
    float acc[4][4];
#pragma unroll
    for (int i = 0; i < 4; i++)
#pragma unroll
        for (int j = 0; j < 4; j++) acc[i][j] = 0.f;

    for (int g0 = 0; g0 < 512; g0 += 64) {
#pragma unroll
        for (int l = 0; l < 4; l++) {
            int idx = tid + l * 256;
            int row = idx >> 4;
            int col = (idx & 15) * 4;
            float4 v = *(const float4*)(keys + row * 512 + g0 + col);
            float* dk = sk + row * 65 + col;
            dk[0] = v.x; dk[1] = v.y; dk[2] = v.z; dk[3] = v.w;
            float4 w = *(const float4*)(FQ + row * 512 + g0 + col);
            float* dq = sq + row * 65 + col;
            dq[0] = w.x; dq[1] = w.y; dq[2] = w.z; dq[3] = w.w;
        }
        __syncthreads();
        for (int g = 0; g < 64; g++) {
            float a[4], bq[4];
#pragma unroll
            for (int i = 0; i < 4; i++) a[i]  = sk[(ty * 4 + i) * 65 + g];
#pragma unroll
            for (int j = 0; j < 4; j++) bq[j] = sq[(tx * 4 + j) * 65 + g];
#pragma unroll
            for (int i = 0; i < 4; i++)
#pragma unroll
                for (int j = 0; j < 4; j++) acc[i][j] += a[i] * bq[j];
        }
        __syncthreads();
    }
#pragma unroll
    for (int i = 0; i < 4; i++)
#pragma unroll
        for (int j = 0; j < 4; j++) {
            int s = ty * 4 + i, q = tx * 4 + j;
            ssc[s * 65 + q] = (q < q_ln) ? acc[i][j] : -INFINITY;
        }
    __syncthreads();

    int warp = tid >> 5, lane = tid & 31;
    for (int si = 0; si < 8; si++) {
        int s = warp * 8 + si;
        float v0 = ssc[s * 65 + lane];
        float v1 = ssc[s * 65 + 32 + lane];
        float mx = fmaxf(v0, v1);
#pragma unroll
        for (int o = 16; o > 0; o >>= 1) mx = fmaxf(mx, __shfl_xor_sync(~0u, mx, o));
        float e0 = expf(v0 - mx), e1 = expf(v1 - mx);
        float su = e0 + e1;
#pragma unroll
        for (int o = 16; o > 0; o >>= 1) su += __shfl_xor_sync(~0u, su, o);
        float sc = (s < s_ln) ? (1.f / su) : 0.f;
        ssc[s * 65 + lane] = e0 * sc;
        ssc[s * 65 + 32 + lane] = e1 * sc;
    }
    __syncthreads();

    if (kb == NS - 1) {
        for (int i = tid; i < 4096; i += 256)
            d_out[i] = ssc[(i >> 6) * 65 + (i & 63)];
    }

    int hcol = tid & 63;
    int qgrp = tid >> 6;
#pragma unroll
    for (int pass = 0; pass < 2; pass++) {
        int qb = qgrp * 8 + pass * 32;
        float hc[8][8];
#pragma unroll
        for (int qi = 0; qi < 8; qi++)
#pragma unroll
            for (int hj = 0; hj < 8; hj++) hc[qi][hj] = 0.f;
        for (int s = 0; s < 64; s++) {
            float4 f0 = *(const float4*)(FS + s * 512 + hcol * 8);
            float4 f1 = *(const float4*)(FS + s * 512 + hcol * 8 + 4);
#pragma unroll
            for (int qi = 0; qi < 8; qi++) {
                float a = ssc[s * 65 + qb + qi];
                hc[qi][0] += a * f0.x; hc[qi][1] += a * f0.y;
                hc[qi][2] += a * f0.z; hc[qi][3] += a * f0.w;
                hc[qi][4] += a * f1.x; hc[qi][5] += a * f1.y;
                hc[qi][6] += a * f1.z; hc[qi][7] += a * f1.w;
            }
        }
#pragma unroll
        for (int qi = 0; qi < 8; qi++) {
            float* dst = shc + (qb + qi) * 520 + hcol * 8;
#pragma unroll
            for (int hj = 0; hj < 8; hj++) dst[hj] = hc[qi][hj];
        }
    }
    __syncthreads();

    for (int qi = 0; qi < 8; qi++) {
        int q = warp + qi * 8;
        float dot = 0.f, nq = 0.f, nh = 0.f, ee = 0.f;
        for (int c = 0; c < 16; c++) {
            int h = lane + c * 32;
            float fq = FQ[q * 512 + h];
            float hv = shc[q * 520 + h];
            dot += fq * hv; nq += fq * fq; nh += hv * hv;
            float dd = fq - hv; ee += dd * dd;
        }
#pragma unroll
        for (int o = 16; o > 0; o >>= 1) {
            dot += __shfl_xor_sync(~0u, dot, o);
            nq  += __shfl_xor_sync(~0u, nq,  o);
            nh  += __shfl_xor_sync(~0u, nh,  o);
            ee  += __shfl_xor_sync(~0u, ee,  o);
        }
        if (lane == 0) {
            float cosv = dot / fmaxf(sqrtf(nq) * sqrtf(nh), 1e-6f);
            float eucv = sqrtf(ee);
            float msk = (q < q_ln) ? 1.f : 0.f;
            g_diff[((size_t)kb * 64 + q) * 2 + 0] = cosv * msk;
            g_diff[((size_t)kb * 64 + q) * 2 + 1] = eucv * msk;
        }
    }
}

// ---------------- dml GRU over diff + FC head: 32 blocks x 5 sequences ----------------
__global__ void __launch_bounds__(256) dml_kernel(
    const float* __restrict__ Wih, const float* __restrict__ Whh,
    const float* __restrict__ bih, const float* __restrict__ bhh,
    const float* __restrict__ fcW, const float* __restrict__ fcb,
    float* __restrict__ d_out)
{
    __shared__ __align__(16) float sh[5][256];
    __shared__ float red[256];
    int tid = threadIdx.x;
    int nb = blockIdx.x * 5;

#pragma unroll
    for (int s = 0; s < 5; s++) sh[s][tid] = 0.f;
    __syncthreads();

    float wi_r0 = Wih[tid * 2],         wi_r1 = Wih[tid * 2 + 1];
    float wi_z0 = Wih[(256 + tid) * 2], wi_z1 = Wih[(256 + tid) * 2 + 1];
    float wi_n0 = Wih[(512 + tid) * 2], wi_n1 = Wih[(512 + tid) * 2 + 1];
    float bi_r = bih[tid], bi_z = bih[256 + tid], bi_n = bih[512 + tid];
    float bh_r = bhh[tid], bh_z = bhh[256 + tid], bh_n = bhh[512 + tid];
    const float* wr = Whh + (size_t)tid * 256;
    const float* wz = Whh + (size_t)(256 + tid) * 256;
    const float* wn = Whh + (size_t)(512 + tid) * 256;

    for (int t = 0; t < 64; t++) {
        uint64_t ar[5] = {0,0,0,0,0}, az[5] = {0,0,0,0,0}, an[5] = {0,0,0,0,0};
        for (int i = 0; i < 256; i += 4) {
            ulonglong2 r2 = *(const ulonglong2*)(wr + i);
            ulonglong2 z2 = *(const ulonglong2*)(wz + i);
            ulonglong2 n2 = *(const ulonglong2*)(wn + i);
#pragma unroll
            for (int s = 0; s < 5; s++) {
                ulonglong2 h2 = *(const ulonglong2*)(&sh[s][i]);
                ffma2(ar[s], r2.x, h2.x); ffma2(ar[s], r2.y, h2.y);
                ffma2(az[s], z2.x, h2.x); ffma2(az[s], z2.y, h2.y);
                ffma2(an[s], n2.x, h2.x); ffma2(an[s], n2.y, h2.y);
            }
        }
        float hn[5];
#pragma unroll
        for (int s = 0; s < 5; s++) {
            int n = nb + s;
            float d0 = g_diff[((size_t)n * 64 + t) * 2 + 0];
            float d1 = g_diff[((size_t)n * 64 + t) * 2 + 1];
            float xr = wi_r0 * d0 + wi_r1 * d1 + bi_r;
            float xz = wi_z0 * d0 + wi_z1 * d1 + bi_z;
            float xn = wi_n0 * d0 + wi_n1 * d1 + bi_n;
            float r  = sigm(xr + upk_sum(ar[s]) + bh_r);
            float z  = sigm(xz + upk_sum(az[s]) + bh_z);
            float ng = tanhf(xn + r * (upk_sum(an[s]) + bh_n));
            hn[s] = (1.f - z) * ng + z * sh[s][tid];
        }
        __syncthreads();
#pragma unroll
        for (int s = 0; s < 5; s++) sh[s][tid] = hn[s];
        __syncthreads();
    }

    float fw = fcW[tid];
    for (int s = 0; s < 5; s++) {
        int n = nb + s;
        red[tid] = fw * sh[s][tid];
        __syncthreads();
        for (int off = 128; off > 0; off >>= 1) {
            if (tid < off) red[tid] += red[tid + off];
            __syncthreads();
        }
        if (tid == 0)
            d_out[4096 + n] = sigm(red[0] + fcb[0]);
        __syncthreads();
    }
}

// ---------------- launcher ----------------
extern "C" void kernel_launch(void* const* d_in, const int* in_sizes, int n_in,
                              void* d_out, int out_size)
{
    const float* feats_S  = (const float*)d_in[0];
    const float* feats_Q  = (const float*)d_in[1];
    const float* Wih_f    = (const float*)d_in[2];
    const float* Whh_f    = (const float*)d_in[3];
    const float* bih_f    = (const float*)d_in[4];
    const float* bhh_f    = (const float*)d_in[5];
    const float* Wih_b    = (const float*)d_in[6];
    const float* Whh_b    = (const float*)d_in[7];
    const float* bih_b    = (const float*)d_in[8];
    const float* bhh_b    = (const float*)d_in[9];
    const float* W_attn   = (const float*)d_in[10];
    const float* attn_b   = (const float*)d_in[11];
    const float* dml_Wih  = (const float*)d_in[12];
    const float* dml_Whh  = (const float*)d_in[13];
    const float* dml_bih  = (const float*)d_in[14];
    const float* dml_bhh  = (const float*)d_in[15];
    const float* fc_W     = (const float*)d_in[16];
    const float* fc_b     = (const float*)d_in[17];
    const int*   s_ln     = (const int*)d_in[18];
    const int*   q_ln     = (const int*)d_in[19];
    float* out = (float*)d_out;

    __nv_bfloat16 *abf, *bbf, *fbf, *wabf;
    float* fptr;
    cudaGetSymbolAddress((void**)&abf, g_Abf);
    cudaGetSymbolAddress((void**)&bbf, g_Bbf);
    cudaGetSymbolAddress((void**)&fbf, g_Fbf);
    cudaGetSymbolAddress((void**)&wabf, g_Wabf);
    cudaGetSymbolAddress((void**)&fptr, g_F);

    // 0) fp32 -> bf16 hi/lo split (3 launches; gemm_mma stays at ncu slot #4)
    convert_split<<<40960, 256>>>(feats_S, abf, abf + AELEMS);
    convert_split<<<8192, 256>>>(feats_Q, abf + (size_t)10240 * DIN,
                                 abf + AELEMS + (size_t)10240 * DIN);
    convert_w<<<6144, 256>>>(Wih_f, Wih_b, bbf, bbf + BELEMS);

    // 1) input projections via bf16 mma.sync, split folded into K'
    cudaFuncSetAttribute(gemm_mma, cudaFuncAttributeMaxDynamicSharedMemorySize, GMM_SMEM);
    gemm_mma<<<dim3(12, 96), 256, GMM_SMEM>>>(bih_f, bih_b);

    // 2) GRU recurrence: 32 seq-groups x 2 directions, 6 seqs each
    bigru_scan<<<64, 256>>>(Whh_f, bhh_f, Whh_b, bhh_b);

    // 3) keys = W_attn(F_S) + bias via bf16 mma (convert F_S + W_attn first)
    convert_split<<<5120, 256>>>(fptr, fbf, fbf + FAEL);
    convert_split<<<256, 256>>>(W_attn, wabf, wabf + WAEL);
    cudaFuncSetAttribute(gemm_keys_mma, cudaFuncAttributeMaxDynamicSharedMemorySize, GMM_SMEM);
    gemm_keys_mma<<<dim3(4, 80), 256, GMM_SMEM>>>(attn_b);

    // 4) scores -> softmax -> A -> Hc -> (cos,euc)
    cudaFuncSetAttribute(attn_kernel, cudaFuncAttributeMaxDynamicSharedMemorySize, ATTN_SMEM);
    attn_kernel<<<160, 256, ATTN_SMEM>>>(s_ln, q_ln, out);

    // 5) dml GRU over (cos,euc) + sigmoid(FC)
    dml_kernel<<<32, 256>>>(dml_Wih, dml_Whh, dml_bih, dml_bhh, fc_W, fc_b, out);
}

// round 9
// speedup vs baseline: 1.6440x; 1.6440x over previous
#include <cuda_runtime.h>
#include <cuda_bf16.h>
#include <math.h>
#include <stdint.h>

// ---------------- problem constants ----------------
#define KK 5
#define BB 32
#define TT 64
#define DIN 4096
#define HH 256            // GRU hidden
#define H2 512            // 2*H
#define NSEQ 192          // 160 S-sequences + 32 Q-sequences
#define NS 160            // K*B
#define MTOT 12288        // NSEQ*TT rows
#define NTOT 1536         // 3H fwd | 3H bwd
#define ATTN_SMEM ((64*65*3 + 64*520)*4)

#define AELEMS ((size_t)MTOT * DIN)
#define BELEMS ((size_t)NTOT * DIN)
#define FAEL   ((size_t)NS * TT * H2)      // F_S elements (10240 x 512)
#define WAEL   ((size_t)H2 * H2)           // W_attn elements

// mma-GEMM tiling: plain bf16 GEMM over K' = 3*K (split planes folded into K)
#define BKC 64
#define NCHUNK (3 * DIN / BKC)       // 192
#define TILE_B (128 * 144)           // 18432 B: 128 rows x (64+8 pad) bf16
#define STAGE_B (2 * TILE_B)         // A tile + B tile = 36864
#define STAGES 3
#define GMM_SMEM (STAGES * STAGE_B)  // 110592 (2 CTAs/SM)
#define NCHUNK2 (3 * H2 / BKC)       // 24 (keys gemm)

// ---------------- scratch (device globals; no allocation allowed) ----------------
__device__ float g_XP[(size_t)NSEQ * TT * NTOT];   // input projections, fwd|bwd gates
__device__ float g_F [(size_t)NSEQ * TT * H2];     // BiGRU features [n][t][fwd256|bwd256]
__device__ float g_keys[(size_t)NS * TT * H2];     // W_attn(F_S)+bias
__device__ float g_diff[(size_t)NS * TT * 2];      // (cos, euc) dml inputs
__device__ __nv_bfloat16 g_Abf[2 * AELEMS];        // bf16 hi|lo planes of inputs
__device__ __nv_bfloat16 g_Bbf[2 * BELEMS];        // bf16 hi|lo planes of Wih_f|Wih_b
__device__ __nv_bfloat16 g_Fbf[2 * FAEL];          // bf16 hi|lo planes of F_S
__device__ __nv_bfloat16 g_Wabf[2 * WAEL];         // bf16 hi|lo planes of W_attn

__device__ __forceinline__ float sigm(float x) { return 1.f / (1.f + expf(-x)); }

__device__ __forceinline__ uint32_t smem_u32(const void* p) {
    uint32_t a;
    asm("{ .reg .u64 t; cvta.to.shared.u64 t, %1; cvt.u32.u64 %0, t; }" : "=r"(a) : "l"(p));
    return a;
}
__device__ __forceinline__ void ldsm4(uint32_t* r, uint32_t a) {
    asm volatile("ldmatrix.sync.aligned.m8n8.x4.shared.b16 {%0,%1,%2,%3}, [%4];"
        : "=r"(r[0]), "=r"(r[1]), "=r"(r[2]), "=r"(r[3]) : "r"(a));
}
__device__ __forceinline__ void mma_bf16(float* c, const uint32_t* a, uint32_t b0, uint32_t b1) {
    asm volatile("mma.sync.aligned.m16n8k16.row.col.f32.bf16.bf16.f32 "
        "{%0,%1,%2,%3}, {%4,%5,%6,%7}, {%8,%9}, {%0,%1,%2,%3};"
        : "+f"(c[0]), "+f"(c[1]), "+f"(c[2]), "+f"(c[3])
        : "r"(a[0]), "r"(a[1]), "r"(a[2]), "r"(a[3]), "r"(b0), "r"(b1));
}
__device__ __forceinline__ void cpasync16(uint32_t s, const void* g) {
    asm volatile("cp.async.cg.shared.global [%0], [%1], 16;" :: "r"(s), "l"(g));
}
#define CP_COMMIT() asm volatile("cp.async.commit_group;" ::: "memory")

// packed f32x2 fma
__device__ __forceinline__ void ffma2(uint64_t& acc, uint64_t a, uint64_t b) {
    asm("fma.rn.f32x2 %0, %1, %2, %0;" : "+l"(acc) : "l"(a), "l"(b));
}
__device__ __forceinline__ float upk_sum(uint64_t v) {
    float x, y;
    asm("mov.b64 {%0,%1}, %2;" : "=f"(x), "=f"(y) : "l"(v));
    return x + y;
}

// ---------------- fp32 -> bf16 hi/lo split ----------------
__global__ void __launch_bounds__(256) convert_split(
    const float* __restrict__ src, __nv_bfloat16* __restrict__ hi, __nv_bfloat16* __restrict__ lo)
{
    size_t i = ((size_t)blockIdx.x * 256 + threadIdx.x) * 4;
    float4 v = *(const float4*)(src + i);
    float vv[4] = { v.x, v.y, v.z, v.w };
    union { __nv_bfloat16 b[4]; uint2 u; } H, L;
#pragma unroll
    for (int j = 0; j < 4; j++) {
        H.b[j] = __float2bfloat16(vv[j]);
        L.b[j] = __float2bfloat16(vv[j] - __bfloat162float(H.b[j]));
    }
    *(uint2*)(hi + i) = H.u;
    *(uint2*)(lo + i) = L.u;
}

// both weight matrices in ONE launch (keeps gemm_mma at launch slot #4 for ncu)
__global__ void __launch_bounds__(256) convert_w(
    const float* __restrict__ wf, const float* __restrict__ wb,
    __nv_bfloat16* __restrict__ hi, __nv_bfloat16* __restrict__ lo)
{
    int bb = blockIdx.x;
    const float* src = wf;
    size_t off = 0;
    if (bb >= 3072) { src = wb; off = (size_t)768 * DIN; bb -= 3072; }
    size_t i = ((size_t)bb * 256 + threadIdx.x) * 4;
    float4 v = *(const float4*)(src + i);
    float vv[4] = { v.x, v.y, v.z, v.w };
    union { __nv_bfloat16 b[4]; uint2 u; } H, L;
#pragma unroll
    for (int j = 0; j < 4; j++) {
        H.b[j] = __float2bfloat16(vv[j]);
        L.b[j] = __float2bfloat16(vv[j] - __bfloat162float(H.b[j]));
    }
    *(uint2*)(hi + off + i) = H.u;
    *(uint2*)(lo + off + i) = L.u;
}

// ---------------- bf16 GEMM via mma.sync, K'=12288, BK=64, 3-stage cp.async ----------------
// grid (12 N-tiles fastest, 96 M-tiles), 256 threads, tile 128x128. (R6 form, no frag dbuf)
__global__ void __launch_bounds__(256, 2) gemm_mma(
    const float* __restrict__ bias1, const float* __restrict__ bias2)
{
    extern __shared__ __align__(128) char smem[];
    uint32_t sbase = smem_u32(smem);
    int tid = threadIdx.x;
    int wid = tid >> 5, lane = tid & 31;
    int warp_m = wid & 1, warp_n = wid >> 1;
    int bn = blockIdx.x * 128, bm = blockIdx.y * 128;

    float acc[4][4][4];
#pragma unroll
    for (int i = 0; i < 4; i++)
#pragma unroll
        for (int j = 0; j < 4; j++)
#pragma unroll
            for (int c = 0; c < 4; c++) acc[i][j][c] = 0.f;

    auto load_stage = [&](int ci, int s) {
        int p = ci % 3;                 // plane phase: 0 Ah*Bh, 1 Ah*Bl, 2 Al*Bh
        int k0 = (ci / 3) * BKC;
        const __nv_bfloat16* Ap = g_Abf + (p == 2 ? AELEMS : 0);
        const __nv_bfloat16* Bp = g_Bbf + (p == 1 ? BELEMS : 0);
        uint32_t sb_s = sbase + s * STAGE_B;
#pragma unroll
        for (int l = 0; l < 8; l++) {
            int idx = tid + l * 256;          // 0..2047
            int isB = idx >> 10;
            int r = (idx >> 3) & 127;
            int seg = idx & 7;
            uint32_t sa = sb_s + isB * TILE_B + r * 144 + seg * 16;
            const __nv_bfloat16* gp = isB
                ? Bp + (size_t)(bn + r) * DIN + k0 + seg * 8
                : Ap + (size_t)(bm + r) * DIN + k0 + seg * 8;
            cpasync16(sa, gp);
        }
        CP_COMMIT();
    };

    auto compute_stage = [&](int s) {
        uint32_t base = sbase + s * STAGE_B;
#pragma unroll
        for (int kh = 0; kh < 4; kh++) {
            uint32_t af[16], bfr[8];
#pragma unroll
            for (int mf = 0; mf < 4; mf++) {
                int row = warp_m * 64 + mf * 16 + (lane & 7) + ((lane >> 3) & 1) * 8;
                uint32_t ad = base + row * 144 + kh * 32 + ((lane >> 4) & 1) * 16;
                ldsm4(&af[mf * 4], ad);
            }
#pragma unroll
            for (int nf2 = 0; nf2 < 2; nf2++) {
                int row = warp_n * 32 + nf2 * 16 + ((lane >> 4) & 1) * 8 + (lane & 7);
                uint32_t bd = base + TILE_B + row * 144 + kh * 32 + ((lane >> 3) & 1) * 16;
                ldsm4(&bfr[nf2 * 4], bd);
            }
#pragma unroll
            for (int mf = 0; mf < 4; mf++)
#pragma unroll
                for (int nf = 0; nf < 4; nf++) {
                    int bi = (nf >> 1) * 4 + (nf & 1) * 2;
                    mma_bf16(acc[mf][nf], &af[mf * 4], bfr[bi], bfr[bi + 1]);
                }
        }
    };

    load_stage(0, 0);
    load_stage(1, 1);

#pragma unroll 1
    for (int ci = 0; ci < NCHUNK; ci++) {
        if (ci < NCHUNK - 1) asm volatile("cp.async.wait_group 1;" ::: "memory");
        else                 asm volatile("cp.async.wait_group 0;" ::: "memory");
        __syncthreads();
        if (ci + 2 < NCHUNK) load_stage(ci + 2, (ci + 2) % STAGES);
        compute_stage(ci % STAGES);
    }

    // epilogue: add bias, write fp32
    float bcol[4][2];
#pragma unroll
    for (int nf = 0; nf < 4; nf++) {
        int col = bn + warp_n * 32 + nf * 8 + (lane & 3) * 2;
        bcol[nf][0] = (col < 768) ? bias1[col] : bias2[col - 768];
        bcol[nf][1] = (col + 1 < 768) ? bias1[col + 1] : bias2[col + 1 - 768];
    }
#pragma unroll
    for (int mf = 0; mf < 4; mf++) {
        int m = bm + warp_m * 64 + mf * 16 + (lane >> 2);
#pragma unroll
        for (int nf = 0; nf < 4; nf++) {
            size_t o = (size_t)m * NTOT + bn + warp_n * 32 + nf * 8 + (lane & 3) * 2;
            float2 v0 = { acc[mf][nf][0] + bcol[nf][0], acc[mf][nf][1] + bcol[nf][1] };
            *(float2*)(g_XP + o) = v0;
            float2 v1 = { acc[mf][nf][2] + bcol[nf][0], acc[mf][nf][3] + bcol[nf][1] };
            *(float2*)(g_XP + o + (size_t)8 * NTOT) = v1;
        }
    }
}

// ---------------- keys GEMM via bf16 mma: g_keys = F_S @ W_attn^T + bias ----------------
// K'=3*512, grid (4 N-tiles, 80 M-tiles). Same proven compute_stage form as gemm_mma.
__global__ void __launch_bounds__(256, 2) gemm_keys_mma(const float* __restrict__ bias1)
{
    extern __shared__ __align__(128) char smem[];
    uint32_t sbase = smem_u32(smem);
    int tid = threadIdx.x;
    int wid = tid >> 5, lane = tid & 31;
    int warp_m = wid & 1, warp_n = wid >> 1;
    int bn = blockIdx.x * 128, bm = blockIdx.y * 128;

    float acc[4][4][4];
#pragma unroll
    for (int i = 0; i < 4; i++)
#pragma unroll
        for (int j = 0; j < 4; j++)
#pragma unroll
            for (int c = 0; c < 4; c++) acc[i][j][c] = 0.f;

    auto load_stage = [&](int ci, int s) {
        int p = ci % 3;
        int k0 = (ci / 3) * BKC;
        const __nv_bfloat16* Ap = g_Fbf + (p == 2 ? FAEL : 0);
        const __nv_bfloat16* Bp = g_Wabf + (p == 1 ? WAEL : 0);
        uint32_t sb_s = sbase + s * STAGE_B;
#pragma unroll
        for (int l = 0; l < 8; l++) {
            int idx = tid + l * 256;
            int isB = idx >> 10;
            int r = (idx >> 3) & 127;
            int seg = idx & 7;
            uint32_t sa = sb_s + isB * TILE_B + r * 144 + seg * 16;
            const __nv_bfloat16* gp = isB
                ? Bp + (size_t)(bn + r) * H2 + k0 + seg * 8
                : Ap + (size_t)(bm + r) * H2 + k0 + seg * 8;
            cpasync16(sa, gp);
        }
        CP_COMMIT();
    };

    auto compute_stage = [&](int s) {
        uint32_t base = sbase + s * STAGE_B;
#pragma unroll
        for (int kh = 0; kh < 4; kh++) {
            uint32_t af[16], bfr[8];
#pragma unroll
            for (int mf = 0; mf < 4; mf++) {
                int row = warp_m * 64 + mf * 16 + (lane & 7) + ((lane >> 3) & 1) * 8;
                uint32_t ad = base + row * 144 + kh * 32 + ((lane >> 4) & 1) * 16;
                ldsm4(&af[mf * 4], ad);
            }
#pragma unroll
            for (int nf2 = 0; nf2 < 2; nf2++) {
                int row = warp_n * 32 + nf2 * 16 + ((lane >> 4) & 1) * 8 + (lane & 7);
                uint32_t bd = base + TILE_B + row * 144 + kh * 32 + ((lane >> 3) & 1) * 16;
                ldsm4(&bfr[nf2 * 4], bd);
            }
#pragma unroll
            for (int mf = 0; mf < 4; mf++)
#pragma unroll
                for (int nf = 0; nf < 4; nf++) {
                    int bi = (nf >> 1) * 4 + (nf & 1) * 2;
                    mma_bf16(acc[mf][nf], &af[mf * 4], bfr[bi], bfr[bi + 1]);
                }
        }
    };

    load_stage(0, 0);
    load_stage(1, 1);

#pragma unroll 1
    for (int ci = 0; ci < NCHUNK2; ci++) {
        if (ci < NCHUNK2 - 1) asm volatile("cp.async.wait_group 1;" ::: "memory");
        else                  asm volatile("cp.async.wait_group 0;" ::: "memory");
        __syncthreads();
        if (ci + 2 < NCHUNK2) load_stage(ci + 2, (ci + 2) % STAGES);
        compute_stage(ci % STAGES);
    }

    float bcol[4][2];
#pragma unroll
    for (int nf = 0; nf < 4; nf++) {
        int col = bn + warp_n * 32 + nf * 8 + (lane & 3) * 2;
        bcol[nf][0] = bias1[col];
        bcol[nf][1] = bias1[col + 1];
    }
#pragma unroll
    for (int mf = 0; mf < 4; mf++) {
        int m = bm + warp_m * 64 + mf * 16 + (lane >> 2);
#pragma unroll
        for (int nf = 0; nf < 4; nf++) {
            size_t o = (size_t)m * H2 + bn + warp_n * 32 + nf * 8 + (lane & 3) * 2;
            float2 v0 = { acc[mf][nf][0] + bcol[nf][0], acc[mf][nf][1] + bcol[nf][1] };
            *(float2*)(g_keys + o) = v0;
            float2 v1 = { acc[mf][nf][2] + bcol[nf][0], acc[mf][nf][3] + bcol[nf][1] };
            *(float2*)(g_keys + o + (size_t)8 * H2) = v1;
        }
    }
}

// ---------------- GRU recurrent scan: 96 blocks = 24 seq-groups x 2 directions, 4 seqs ----------------
__global__ void __launch_bounds__(256) bigru_scan(
    const float* __restrict__ Whh_f, const float* __restrict__ bhh_f,
    const float* __restrict__ Whh_b, const float* __restrict__ bhh_b)
{
    __shared__ __align__(16) float sh[4][256];
    int tid = threadIdx.x;
    int d = blockIdx.x & 1;
    int nb = (blockIdx.x >> 1) * 4;

#pragma unroll
    for (int s = 0; s < 4; s++) sh[s][tid] = 0.f;
    __syncthreads();

    const float* W  = d ? Whh_b : Whh_f;
    const float* BH = d ? bhh_b : bhh_f;
    float bh_r = BH[tid], bh_z = BH[256 + tid], bh_n = BH[512 + tid];
    const float* wr = W + (size_t)tid * 256;
    const float* wz = W + (size_t)(256 + tid) * 256;
    const float* wn = W + (size_t)(512 + tid) * 256;

    for (int t = 0; t < 64; t++) {
        int tt = d ? (63 - t) : t;
        uint64_t ar[4] = {0,0,0,0}, az[4] = {0,0,0,0}, an[4] = {0,0,0,0};
        for (int i = 0; i < 256; i += 4) {
            ulonglong2 r2 = *(const ulonglong2*)(wr + i);
            ulonglong2 z2 = *(const ulonglong2*)(wz + i);
            ulonglong2 n2 = *(const ulonglong2*)(wn + i);
#pragma unroll
            for (int s = 0; s < 4; s++) {
                ulonglong2 h2 = *(const ulonglong2*)(&sh[s][i]);
                ffma2(ar[s], r2.x, h2.x); ffma2(ar[s], r2.y, h2.y);
                ffma2(az[s], z2.x, h2.x); ffma2(az[s], z2.y, h2.y);
                ffma2(an[s], n2.x, h2.x); ffma2(an[s], n2.y, h2.y);
            }
        }
        float hn[4];
#pragma unroll
        for (int s = 0; s < 4; s++) {
            int n = nb + s;
            const float* xp = g_XP + ((size_t)n * 64 + tt) * NTOT + d * 768;
            float r  = sigm(xp[tid]       + upk_sum(ar[s]) + bh_r);
            float z  = sigm(xp[256 + tid] + upk_sum(az[s]) + bh_z);
            float ng = tanhf(xp[512 + tid] + r * (upk_sum(an[s]) + bh_n));
            hn[s] = (1.f - z) * ng + z * sh[s][tid];
        }
        __syncthreads();
#pragma unroll
        for (int s = 0; s < 4; s++) {
            sh[s][tid] = hn[s];
            g_F[((size_t)(nb + s) * 64 + tt) * 512 + d * 256 + tid] = hn[s];
        }
        __syncthreads();
    }
}

// ---------------- attention + softmax + Hc + cos/euc, one block per (k,b) ----------------
__global__ void __launch_bounds__(256) attn_kernel(
    const int* __restrict__ s_ln_arr, const int* __restrict__ q_ln_arr,
    float* __restrict__ d_out)
{
    extern __shared__ float sm[];
    float* ssc = sm;                 // [64][65] scores -> A
    float* sk  = sm + 64 * 65;       // [64][65] keys tile
    float* sq  = sk + 64 * 65;       // [64][65] F_Q tile
    float* shc = sq + 64 * 65;       // [64][520] Hc

    int kb = blockIdx.x;
    int b = kb & 31;
    int tid = threadIdx.x;
    int q_ln = q_ln_arr[b];
    int s_ln = s_ln_arr[kb];

    const float* keys = g_keys + (size_t)kb * 64 * 512;
    const float* FQ   = g_F + ((size_t)(160 + b) * 64) * 512;
    const float* FS   = g_F + ((size_t)kb * 64) * 512;

    int tx = tid & 15, ty = tid >> 4;
    float acc[4][4];
#pragma unroll
    for (int i = 0; i < 4; i++)
#pragma unroll
        for (int j = 0; j < 4; j++) acc[i][j] = 0.f;

    for (int g0 = 0; g0 < 512; g0 += 64) {
#pragma unroll
        for (int l = 0; l < 4; l++) {
            int idx = tid + l * 256;
            int row = idx >> 4;
            int col = (idx & 15) * 4;
            float4 v = *(const float4*)(keys + row * 512 + g0 + col);
            float* dk = sk + row * 65 + col;
            dk[0] = v.x; dk[1] = v.y; dk[2] = v.z; dk[3] = v.w;
            float4 w = *(const float4*)(FQ + row * 512 + g0 + col);
            float* dq = sq + row * 65 + col;
            dq[0] = w.x; dq[1] = w.y; dq[2] = w.z; dq[3] = w.w;
        }
        __syncthreads();
        for (int g = 0; g < 64; g++) {
            float a[4], bq[4];
#pragma unroll
            for (int i = 0; i < 4; i++) a[i]  = sk[(ty * 4 + i) * 65 + g];
#pragma unroll
            for (int j = 0; j < 4; j++) bq[j] = sq[(tx * 4 + j) * 65 + g];
#pragma unroll
            for (int i = 0; i < 4; i++)
#pragma unroll
                for (int j = 0; j < 4; j++) acc[i][j] += a[i] * bq[j];
        }
        __syncthreads();
    }
#pragma unroll
    for (int i = 0; i < 4; i++)
#pragma unroll
        for (int j = 0; j < 4; j++) {
            int s = ty * 4 + i, q = tx * 4 + j;
            ssc[s * 65 + q] = (q < q_ln) ? acc[i][j] : -INFINITY;
        }
    __syncthreads();

    int warp = tid >> 5, lane = tid & 31;
    for (int si = 0; si < 8; si++) {
        int s = warp * 8 + si;
        float v0 = ssc[s * 65 + lane];
        float v1 = ssc[s * 65 + 32 + lane];
        float mx = fmaxf(v0, v1);
#pragma unroll
        for (int o = 16; o > 0; o >>= 1) mx = fmaxf(mx, __shfl_xor_sync(~0u, mx, o));
        float e0 = expf(v0 - mx), e1 = expf(v1 - mx);
        float su = e0 + e1;
#pragma unroll
        for (int o = 16; o > 0; o >>= 1) su += __shfl_xor_sync(~0u, su, o);
        float sc = (s < s_ln) ? (1.f / su) : 0.f;
        ssc[s * 65 + lane] = e0 * sc;
        ssc[s * 65 + 32 + lane] = e1 * sc;
    }
    __syncthreads();

    if (kb == NS - 1) {
        for (int i = tid; i < 4096; i += 256)
            d_out[i] = ssc[(i >> 6) * 65 + (i & 63)];
    }

    int hcol = tid & 63;
    int qgrp = tid >> 6;
#pragma unroll
    for (int pass = 0; pass < 2; pass++) {
        int qb = qgrp * 8 + pass * 32;
        float hc[8][8];
#pragma unroll
        for (int qi = 0; qi < 8; qi++)
#pragma unroll
            for (int hj = 0; hj < 8; hj++) hc[qi][hj] = 0.f;
        for (int s = 0; s < 64; s++) {
            float4 f0 = *(const float4*)(FS + s * 512 + hcol * 8);
            float4 f1 = *(const float4*)(FS + s * 512 + hcol * 8 + 4);
#pragma unroll
            for (int qi = 0; qi < 8; qi++) {
                float a = ssc[s * 65 + qb + qi];
                hc[qi][0] += a * f0.x; hc[qi][1] += a * f0.y;
                hc[qi][2] += a * f0.z; hc[qi][3] += a * f0.w;
                hc[qi][4] += a * f1.x; hc[qi][5] += a * f1.y;
                hc[qi][6] += a * f1.z; hc[qi][7] += a * f1.w;
            }
        }
#pragma unroll
        for (int qi = 0; qi < 8; qi++) {
            float* dst = shc + (qb + qi) * 520 + hcol * 8;
#pragma unroll
            for (int hj = 0; hj < 8; hj++) dst[hj] = hc[qi][hj];
        }
    }
    __syncthreads();

    for (int qi = 0; qi < 8; qi++) {
        int q = warp + qi * 8;
        float dot = 0.f, nq = 0.f, nh = 0.f, ee = 0.f;
        for (int c = 0; c < 16; c++) {
            int h = lane + c * 32;
            float fq = FQ[q * 512 + h];
            float hv = shc[q * 520 + h];
            dot += fq * hv; nq += fq * fq; nh += hv * hv;
            float dd = fq - hv; ee += dd * dd;
        }
#pragma unroll
        for (int o = 16; o > 0; o >>= 1) {
            dot += __shfl_xor_sync(~0u, dot, o);
            nq  += __shfl_xor_sync(~0u, nq,  o);
            nh  += __shfl_xor_sync(~0u, nh,  o);
            ee  += __shfl_xor_sync(~0u, ee,  o);
        }
        if (lane == 0) {
            float cosv = dot / fmaxf(sqrtf(nq) * sqrtf(nh), 1e-6f);
            float eucv = sqrtf(ee);
            float msk = (q < q_ln) ? 1.f : 0.f;
            g_diff[((size_t)kb * 64 + q) * 2 + 0] = cosv * msk;
            g_diff[((size_t)kb * 64 + q) * 2 + 1] = eucv * msk;
        }
    }
}

// ---------------- dml GRU over diff + FC head: 40 blocks x 4 sequences ----------------
__global__ void __launch_bounds__(256) dml_kernel(
    const float* __restrict__ Wih, const float* __restrict__ Whh,
    const float* __restrict__ bih, const float* __restrict__ bhh,
    const float* __restrict__ fcW, const float* __restrict__ fcb,
    float* __restrict__ d_out)
{
    __shared__ __align__(16) float sh[4][256];
    __shared__ float red[256];
    int tid = threadIdx.x;
    int nb = blockIdx.x * 4;

#pragma unroll
    for (int s = 0; s < 4; s++) sh[s][tid] = 0.f;
    __syncthreads();

    float wi_r0 = Wih[tid * 2],         wi_r1 = Wih[tid * 2 + 1];
    float wi_z0 = Wih[(256 + tid) * 2], wi_z1 = Wih[(256 + tid) * 2 + 1];
    float wi_n0 = Wih[(512 + tid) * 2], wi_n1 = Wih[(512 + tid) * 2 + 1];
    float bi_r = bih[tid], bi_z = bih[256 + tid], bi_n = bih[512 + tid];
    float bh_r = bhh[tid], bh_z = bhh[256 + tid], bh_n = bhh[512 + tid];
    const float* wr = Whh + (size_t)tid * 256;
    const float* wz = Whh + (size_t)(256 + tid) * 256;
    const float* wn = Whh + (size_t)(512 + tid) * 256;

    for (int t = 0; t < 64; t++) {
        uint64_t ar[4] = {0,0,0,0}, az[4] = {0,0,0,0}, an[4] = {0,0,0,0};
        for (int i = 0; i < 256; i += 4) {
            ulonglong2 r2 = *(const ulonglong2*)(wr + i);
            ulonglong2 z2 = *(const ulonglong2*)(wz + i);
            ulonglong2 n2 = *(const ulonglong2*)(wn + i);
#pragma unroll
            for (int s = 0; s < 4; s++) {
                ulonglong2 h2 = *(const ulonglong2*)(&sh[s][i]);
                ffma2(ar[s], r2.x, h2.x); ffma2(ar[s], r2.y, h2.y);
                ffma2(az[s], z2.x, h2.x); ffma2(az[s], z2.y, h2.y);
                ffma2(an[s], n2.x, h2.x); ffma2(an[s], n2.y, h2.y);
            }
        }
        float hn[4];
#pragma unroll
        for (int s = 0; s < 4; s++) {
            int n = nb + s;
            float d0 = g_diff[((size_t)n * 64 + t) * 2 + 0];
            float d1 = g_diff[((size_t)n * 64 + t) * 2 + 1];
            float xr = wi_r0 * d0 + wi_r1 * d1 + bi_r;
            float xz = wi_z0 * d0 + wi_z1 * d1 + bi_z;
            float xn = wi_n0 * d0 + wi_n1 * d1 + bi_n;
            float r  = sigm(xr + upk_sum(ar[s]) + bh_r);
            float z  = sigm(xz + upk_sum(az[s]) + bh_z);
            float ng = tanhf(xn + r * (upk_sum(an[s]) + bh_n));
            hn[s] = (1.f - z) * ng + z * sh[s][tid];
        }
        __syncthreads();
#pragma unroll
        for (int s = 0; s < 4; s++) sh[s][tid] = hn[s];
        __syncthreads();
    }

    float fw = fcW[tid];
    for (int s = 0; s < 4; s++) {
        int n = nb + s;
        red[tid] = fw * sh[s][tid];
        __syncthreads();
        for (int off = 128; off > 0; off >>= 1) {
            if (tid < off) red[tid] += red[tid + off];
            __syncthreads();
        }
        if (tid == 0)
            d_out[4096 + n] = sigm(red[0] + fcb[0]);
        __syncthreads();
    }
}

// ---------------- launcher ----------------
extern "C" void kernel_launch(void* const* d_in, const int* in_sizes, int n_in,
                              void* d_out, int out_size)
{
    const float* feats_S  = (const float*)d_in[0];
    const float* feats_Q  = (const float*)d_in[1];
    const float* Wih_f    = (const float*)d_in[2];
    const float* Whh_f    = (const float*)d_in[3];
    const float* bih_f    = (const float*)d_in[4];
    const float* bhh_f    = (const float*)d_in[5];
    const float* Wih_b    = (const float*)d_in[6];
    const float* Whh_b    = (const float*)d_in[7];
    const float* bih_b    = (const float*)d_in[8];
    const float* bhh_b    = (const float*)d_in[9];
    const float* W_attn   = (const float*)d_in[10];
    const float* attn_b   = (const float*)d_in[11];
    const float* dml_Wih  = (const float*)d_in[12];
    const float* dml_Whh  = (const float*)d_in[13];
    const float* dml_bih  = (const float*)d_in[14];
    const float* dml_bhh  = (const float*)d_in[15];
    const float* fc_W     = (const float*)d_in[16];
    const float* fc_b     = (const float*)d_in[17];
    const int*   s_ln     = (const int*)d_in[18];
    const int*   q_ln     = (const int*)d_in[19];
    float* out = (float*)d_out;

    __nv_bfloat16 *abf, *bbf, *fbf, *wabf;
    float* fptr;
    cudaGetSymbolAddress((void**)&abf, g_Abf);
    cudaGetSymbolAddress((void**)&bbf, g_Bbf);
    cudaGetSymbolAddress((void**)&fbf, g_Fbf);
    cudaGetSymbolAddress((void**)&wabf, g_Wabf);
    cudaGetSymbolAddress((void**)&fptr, g_F);

    // 0) fp32 -> bf16 hi/lo split (3 launches; gemm_mma stays at ncu slot #4)
    convert_split<<<40960, 256>>>(feats_S, abf, abf + AELEMS);
    convert_split<<<8192, 256>>>(feats_Q, abf + (size_t)10240 * DIN,
                                 abf + AELEMS + (size_t)10240 * DIN);
    convert_w<<<6144, 256>>>(Wih_f, Wih_b, bbf, bbf + BELEMS);

    // 1) input projections via bf16 mma.sync, split folded into K'
    cudaFuncSetAttribute(gemm_mma, cudaFuncAttributeMaxDynamicSharedMemorySize, GMM_SMEM);
    gemm_mma<<<dim3(12, 96), 256, GMM_SMEM>>>(bih_f, bih_b);

    // 2) GRU recurrence: 24 seq-groups x 2 directions, 4 seqs each (R6 config)
    bigru_scan<<<96, 256>>>(Whh_f, bhh_f, Whh_b, bhh_b);

    // 3) keys = W_attn(F_S) + bias via bf16 mma (convert F_S + W_attn first)
    convert_split<<<5120, 256>>>(fptr, fbf, fbf + FAEL);
    convert_split<<<256, 256>>>(W_attn, wabf, wabf + WAEL);
    cudaFuncSetAttribute(gemm_keys_mma, cudaFuncAttributeMaxDynamicSharedMemorySize, GMM_SMEM);
    gemm_keys_mma<<<dim3(4, 80), 256, GMM_SMEM>>>(attn_b);

    // 4) scores -> softmax -> A -> Hc -> (cos,euc)
    cudaFuncSetAttribute(attn_kernel, cudaFuncAttributeMaxDynamicSharedMemorySize, ATTN_SMEM);
    attn_kernel<<<160, 256, ATTN_SMEM>>>(s_ln, q_ln, out);

    // 5) dml GRU over (cos,euc) + sigmoid(FC)
    dml_kernel<<<40, 256>>>(dml_Wih, dml_Whh, dml_bih, dml_bhh, fc_W, fc_b, out);
}

// round 11
// speedup vs baseline: 1.6551x; 1.0068x over previous
#include <cuda_runtime.h>
#include <cuda_bf16.h>
#include <math.h>
#include <stdint.h>

// ---------------- problem constants ----------------
#define KK 5
#define BB 32
#define TT 64
#define DIN 4096
#define HH 256            // GRU hidden
#define H2 512            // 2*H
#define NSEQ 192          // 160 S-sequences + 32 Q-sequences
#define NS 160            // K*B
#define MTOT 12288        // NSEQ*TT rows
#define NTOT 1536         // 3H fwd | 3H bwd
#define ATTN_SMEM ((64*65*3 + 64*520)*4)

#define AELEMS ((size_t)MTOT * DIN)
#define BELEMS ((size_t)NTOT * DIN)
#define FAEL   ((size_t)NS * TT * H2)      // F_S elements (10240 x 512)
#define WAEL   ((size_t)H2 * H2)           // W_attn elements

// superchunk gemm tiling: per k0 of 32, stage 4 planes (Ah|Al|Bh|Bl), 3 plane-passes
#define NSC 128                      // 4096/32 superchunks
#define PLANE_B 10240                // 128 rows x 80B (64B data + 16B pad)
#define STAGE_B (4 * PLANE_B)        // 40960
#define GMM_SMEM (2 * STAGE_B)       // 81920, 2 stages, 2 CTAs/SM

// keys gemm (R8 proven form): BK=64, 3-stage, K'=3*512
#define BKC 64
#define KTILE_B (128 * 144)          // 18432
#define KSTAGE_B (2 * KTILE_B)       // 36864
#define KEYS_SMEM (3 * KSTAGE_B)     // 110592
#define NCHUNK2 (3 * H2 / BKC)       // 24

// ---------------- scratch (device globals; no allocation allowed) ----------------
__device__ float g_XP[(size_t)NSEQ * TT * NTOT];   // input projections, fwd|bwd gates
__device__ float g_F [(size_t)NSEQ * TT * H2];     // BiGRU features [n][t][fwd256|bwd256]
__device__ float g_keys[(size_t)NS * TT * H2];     // W_attn(F_S)+bias
__device__ float g_diff[(size_t)NS * TT * 2];      // (cos, euc) dml inputs
__device__ __nv_bfloat16 g_Abf[2 * AELEMS];        // bf16 hi|lo planes of inputs
__device__ __nv_bfloat16 g_Bbf[2 * BELEMS];        // bf16 hi|lo planes of Wih_f|Wih_b
__device__ __nv_bfloat16 g_Fbf[2 * FAEL];          // bf16 hi|lo planes of F_S
__device__ __nv_bfloat16 g_Wabf[2 * WAEL];         // bf16 hi|lo planes of W_attn

__device__ __forceinline__ float sigm(float x) { return 1.f / (1.f + expf(-x)); }

__device__ __forceinline__ uint32_t smem_u32(const void* p) {
    uint32_t a;
    asm("{ .reg .u64 t; cvta.to.shared.u64 t, %1; cvt.u32.u64 %0, t; }" : "=r"(a) : "l"(p));
    return a;
}
__device__ __forceinline__ void ldsm4(uint32_t* r, uint32_t a) {
    asm volatile("ldmatrix.sync.aligned.m8n8.x4.shared.b16 {%0,%1,%2,%3}, [%4];"
        : "=r"(r[0]), "=r"(r[1]), "=r"(r[2]), "=r"(r[3]) : "r"(a));
}
__device__ __forceinline__ void mma_bf16(float* c, const uint32_t* a, uint32_t b0, uint32_t b1) {
    asm volatile("mma.sync.aligned.m16n8k16.row.col.f32.bf16.bf16.f32 "
        "{%0,%1,%2,%3}, {%4,%5,%6,%7}, {%8,%9}, {%0,%1,%2,%3};"
        : "+f"(c[0]), "+f"(c[1]), "+f"(c[2]), "+f"(c[3])
        : "r"(a[0]), "r"(a[1]), "r"(a[2]), "r"(a[3]), "r"(b0), "r"(b1));
}
__device__ __forceinline__ void cpasync16(uint32_t s, const void* g) {
    asm volatile("cp.async.cg.shared.global [%0], [%1], 16;" :: "r"(s), "l"(g));
}
#define CP_COMMIT() asm volatile("cp.async.commit_group;" ::: "memory")

// packed f32x2 fma
__device__ __forceinline__ void ffma2(uint64_t& acc, uint64_t a, uint64_t b) {
    asm("fma.rn.f32x2 %0, %1, %2, %0;" : "+l"(acc) : "l"(a), "l"(b));
}
__device__ __forceinline__ float upk_sum(uint64_t v) {
    float x, y;
    asm("mov.b64 {%0,%1}, %2;" : "=f"(x), "=f"(y) : "l"(v));
    return x + y;
}

// ---------------- fp32 -> bf16 hi/lo split ----------------
__global__ void __launch_bounds__(256) convert_split(
    const float* __restrict__ src, __nv_bfloat16* __restrict__ hi, __nv_bfloat16* __restrict__ lo)
{
    size_t i = ((size_t)blockIdx.x * 256 + threadIdx.x) * 4;
    float4 v = *(const float4*)(src + i);
    float vv[4] = { v.x, v.y, v.z, v.w };
    union { __nv_bfloat16 b[4]; uint2 u; } H, L;
#pragma unroll
    for (int j = 0; j < 4; j++) {
        H.b[j] = __float2bfloat16(vv[j]);
        L.b[j] = __float2bfloat16(vv[j] - __bfloat162float(H.b[j]));
    }
    *(uint2*)(hi + i) = H.u;
    *(uint2*)(lo + i) = L.u;
}

// both weight matrices in ONE launch (keeps gemm_mma at launch slot #4 for ncu)
__global__ void __launch_bounds__(256) convert_w(
    const float* __restrict__ wf, const float* __restrict__ wb,
    __nv_bfloat16* __restrict__ hi, __nv_bfloat16* __restrict__ lo)
{
    int bb = blockIdx.x;
    const float* src = wf;
    size_t off = 0;
    if (bb >= 3072) { src = wb; off = (size_t)768 * DIN; bb -= 3072; }
    size_t i = ((size_t)bb * 256 + threadIdx.x) * 4;
    float4 v = *(const float4*)(src + i);
    float vv[4] = { v.x, v.y, v.z, v.w };
    union { __nv_bfloat16 b[4]; uint2 u; } H, L;
#pragma unroll
    for (int j = 0; j < 4; j++) {
        H.b[j] = __float2bfloat16(vv[j]);
        L.b[j] = __float2bfloat16(vv[j] - __bfloat162float(H.b[j]));
    }
    *(uint2*)(hi + off + i) = H.u;
    *(uint2*)(lo + off + i) = L.u;
}

// ---------------- bf16 superchunk GEMM via mma.sync ----------------
// grid (12 N-tiles fastest, 96 M-tiles), 256 threads, tile 128x128.
// Per superchunk (k0 of 32): stage Ah|Al|Bh|Bl once, run 3 plane passes (hh, hl, lh).
__global__ void __launch_bounds__(256, 2) gemm_mma(
    const float* __restrict__ bias1, const float* __restrict__ bias2)
{
    extern __shared__ __align__(128) char smem[];
    uint32_t sbase = smem_u32(smem);
    int tid = threadIdx.x;
    int wid = tid >> 5, lane = tid & 31;
    int warp_m = wid & 1, warp_n = wid >> 1;
    int bn = blockIdx.x * 128, bm = blockIdx.y * 128;

    float acc[4][4][4];
#pragma unroll
    for (int i = 0; i < 4; i++)
#pragma unroll
        for (int j = 0; j < 4; j++)
#pragma unroll
            for (int c = 0; c < 4; c++) acc[i][j][c] = 0.f;

    // per-warp ldsm invariants (80B rows)
    uint32_t aoff = (uint32_t)(warp_m * 64 + (lane & 7) + ((lane >> 3) & 1) * 8) * 80
                  + ((lane >> 4) & 1) * 16;
    uint32_t boff = (uint32_t)(warp_n * 32 + ((lane >> 4) & 1) * 8 + (lane & 7)) * 80
                  + ((lane >> 3) & 1) * 16;

    auto load_stage = [&](int sc, int st) {
        int k0 = sc * 32;
        uint32_t sb_s = sbase + st * STAGE_B;
#pragma unroll
        for (int l = 0; l < 8; l++) {
            int idx = tid + l * 256;          // 0..2047
            int pl = idx >> 9;                // 0:Ah 1:Al 2:Bh 3:Bl
            int rem = idx & 511;
            int r = rem >> 2;
            int seg = rem & 3;
            uint32_t sa = sb_s + pl * PLANE_B + r * 80 + seg * 16;
            const __nv_bfloat16* gp;
            if (pl == 0)      gp = g_Abf + (size_t)(bm + r) * DIN + k0 + seg * 8;
            else if (pl == 1) gp = g_Abf + AELEMS + (size_t)(bm + r) * DIN + k0 + seg * 8;
            else if (pl == 2) gp = g_Bbf + (size_t)(bn + r) * DIN + k0 + seg * 8;
            else              gp = g_Bbf + BELEMS + (size_t)(bn + r) * DIN + k0 + seg * 8;
            cpasync16(sa, gp);
        }
        CP_COMMIT();
    };

    auto compute_stage = [&](int st) {
        uint32_t base = sbase + st * STAGE_B;
#pragma unroll
        for (int pass = 0; pass < 3; pass++) {
            uint32_t abase = base + ((pass == 2) ? PLANE_B : 0);
            uint32_t bbase = base + ((pass == 1) ? 3 * PLANE_B : 2 * PLANE_B);
#pragma unroll
            for (int kh = 0; kh < 2; kh++) {
                uint32_t af[16], bfr[8];
#pragma unroll
                for (int mf = 0; mf < 4; mf++)
                    ldsm4(&af[mf * 4], abase + aoff + mf * 1280 + kh * 32);
#pragma unroll
                for (int nf2 = 0; nf2 < 2; nf2++)
                    ldsm4(&bfr[nf2 * 4], bbase + boff + nf2 * 1280 + kh * 32);
#pragma unroll
                for (int mf = 0; mf < 4; mf++)
#pragma unroll
                    for (int nf = 0; nf < 4; nf++) {
                        int bi = (nf >> 1) * 4 + (nf & 1) * 2;
                        mma_bf16(acc[mf][nf], &af[mf * 4], bfr[bi], bfr[bi + 1]);
                    }
            }
        }
    };

    load_stage(0, 0);

#pragma unroll 1
    for (int sc = 0; sc < NSC; sc++) {
        asm volatile("cp.async.wait_group 0;" ::: "memory");
        __syncthreads();
        if (sc + 1 < NSC) load_stage(sc + 1, (sc + 1) & 1);
        compute_stage(sc & 1);
    }

    // epilogue: add bias, write fp32
    float bcol[4][2];
#pragma unroll
    for (int nf = 0; nf < 4; nf++) {
        int col = bn + warp_n * 32 + nf * 8 + (lane & 3) * 2;
        bcol[nf][0] = (col < 768) ? bias1[col] : bias2[col - 768];
        bcol[nf][1] = (col + 1 < 768) ? bias1[col + 1] : bias2[col + 1 - 768];
    }
#pragma unroll
    for (int mf = 0; mf < 4; mf++) {
        int m = bm + warp_m * 64 + mf * 16 + (lane >> 2);
#pragma unroll
        for (int nf = 0; nf < 4; nf++) {
            size_t o = (size_t)m * NTOT + bn + warp_n * 32 + nf * 8 + (lane & 3) * 2;
            float2 v0 = { acc[mf][nf][0] + bcol[nf][0], acc[mf][nf][1] + bcol[nf][1] };
            *(float2*)(g_XP + o) = v0;
            float2 v1 = { acc[mf][nf][2] + bcol[nf][0], acc[mf][nf][3] + bcol[nf][1] };
            *(float2*)(g_XP + o + (size_t)8 * NTOT) = v1;
        }
    }
}

// ---------------- keys GEMM via bf16 mma (R8 proven form): g_keys = F_S @ W_attn^T + bias ----------------
__global__ void __launch_bounds__(256, 2) gemm_keys_mma(const float* __restrict__ bias1)
{
    extern __shared__ __align__(128) char smem[];
    uint32_t sbase = smem_u32(smem);
    int tid = threadIdx.x;
    int wid = tid >> 5, lane = tid & 31;
    int warp_m = wid & 1, warp_n = wid >> 1;
    int bn = blockIdx.x * 128, bm = blockIdx.y * 128;

    float acc[4][4][4];
#pragma unroll
    for (int i = 0; i < 4; i++)
#pragma unroll
        for (int j = 0; j < 4; j++)
#pragma unroll
            for (int c = 0; c < 4; c++) acc[i][j][c] = 0.f;

    auto load_stage = [&](int ci, int s) {
        int p = ci % 3;
        int k0 = (ci / 3) * BKC;
        const __nv_bfloat16* Ap = g_Fbf + (p == 2 ? FAEL : 0);
        const __nv_bfloat16* Bp = g_Wabf + (p == 1 ? WAEL : 0);
        uint32_t sb_s = sbase + s * KSTAGE_B;
#pragma unroll
        for (int l = 0; l < 8; l++) {
            int idx = tid + l * 256;
            int isB = idx >> 10;
            int r = (idx >> 3) & 127;
            int seg = idx & 7;
            uint32_t sa = sb_s + isB * KTILE_B + r * 144 + seg * 16;
            const __nv_bfloat16* gp = isB
                ? Bp + (size_t)(bn + r) * H2 + k0 + seg * 8
                : Ap + (size_t)(bm + r) * H2 + k0 + seg * 8;
            cpasync16(sa, gp);
        }
        CP_COMMIT();
    };

    auto compute_stage = [&](int s) {
        uint32_t base = sbase + s * KSTAGE_B;
#pragma unroll
        for (int kh = 0; kh < 4; kh++) {
            uint32_t af[16], bfr[8];
#pragma unroll
            for (int mf = 0; mf < 4; mf++) {
                int row = warp_m * 64 + mf * 16 + (lane & 7) + ((lane >> 3) & 1) * 8;
                uint32_t ad = base + row * 144 + kh * 32 + ((lane >> 4) & 1) * 16;
                ldsm4(&af[mf * 4], ad);
            }
#pragma unroll
            for (int nf2 = 0; nf2 < 2; nf2++) {
                int row = warp_n * 32 + nf2 * 16 + ((lane >> 4) & 1) * 8 + (lane & 7);
                uint32_t bd = base + KTILE_B + row * 144 + kh * 32 + ((lane >> 3) & 1) * 16;
                ldsm4(&bfr[nf2 * 4], bd);
            }
#pragma unroll
            for (int mf = 0; mf < 4; mf++)
#pragma unroll
                for (int nf = 0; nf < 4; nf++) {
                    int bi = (nf >> 1) * 4 + (nf & 1) * 2;
                    mma_bf16(acc[mf][nf], &af[mf * 4], bfr[bi], bfr[bi + 1]);
                }
        }
    };

    load_stage(0, 0);
    load_stage(1, 1);

#pragma unroll 1
    for (int ci = 0; ci < NCHUNK2; ci++) {
        if (ci < NCHUNK2 - 1) asm volatile("cp.async.wait_group 1;" ::: "memory");
        else                  asm volatile("cp.async.wait_group 0;" ::: "memory");
        __syncthreads();
        if (ci + 2 < NCHUNK2) load_stage(ci + 2, (ci + 2) % 3);
        compute_stage(ci % 3);
    }

    float bcol[4][2];
#pragma unroll
    for (int nf = 0; nf < 4; nf++) {
        int col = bn + warp_n * 32 + nf * 8 + (lane & 3) * 2;
        bcol[nf][0] = bias1[col];
        bcol[nf][1] = bias1[col + 1];
    }
#pragma unroll
    for (int mf = 0; mf < 4; mf++) {
        int m = bm + warp_m * 64 + mf * 16 + (lane >> 2);
#pragma unroll
        for (int nf = 0; nf < 4; nf++) {
            size_t o = (size_t)m * H2 + bn + warp_n * 32 + nf * 8 + (lane & 3) * 2;
            float2 v0 = { acc[mf][nf][0] + bcol[nf][0], acc[mf][nf][1] + bcol[nf][1] };
            *(float2*)(g_keys + o) = v0;
            float2 v1 = { acc[mf][nf][2] + bcol[nf][0], acc[mf][nf][3] + bcol[nf][1] };
            *(float2*)(g_keys + o + (size_t)8 * H2) = v1;
        }
    }
}

// ---------------- GRU recurrent scan: 96 blocks = 24 seq-groups x 2 directions, 4 seqs ----------------
__global__ void __launch_bounds__(256) bigru_scan(
    const float* __restrict__ Whh_f, const float* __restrict__ bhh_f,
    const float* __restrict__ Whh_b, const float* __restrict__ bhh_b)
{
    __shared__ __align__(16) float sh[4][256];
    int tid = threadIdx.x;
    int d = blockIdx.x & 1;
    int nb = (blockIdx.x >> 1) * 4;

#pragma unroll
    for (int s = 0; s < 4; s++) sh[s][tid] = 0.f;
    __syncthreads();

    const float* W  = d ? Whh_b : Whh_f;
    const float* BH = d ? bhh_b : bhh_f;
    float bh_r = BH[tid], bh_z = BH[256 + tid], bh_n = BH[512 + tid];
    const float* wr = W + (size_t)tid * 256;
    const float* wz = W + (size_t)(256 + tid) * 256;
    const float* wn = W + (size_t)(512 + tid) * 256;

    for (int t = 0; t < 64; t++) {
        int tt = d ? (63 - t) : t;
        uint64_t ar[4] = {0,0,0,0}, az[4] = {0,0,0,0}, an[4] = {0,0,0,0};
        for (int i = 0; i < 256; i += 4) {
            ulonglong2 r2 = *(const ulonglong2*)(wr + i);
            ulonglong2 z2 = *(const ulonglong2*)(wz + i);
            ulonglong2 n2 = *(const ulonglong2*)(wn + i);
#pragma unroll
            for (int s = 0; s < 4; s++) {
                ulonglong2 h2 = *(const ulonglong2*)(&sh[s][i]);
                ffma2(ar[s], r2.x, h2.x); ffma2(ar[s], r2.y, h2.y);
                ffma2(az[s], z2.x, h2.x); ffma2(az[s], z2.y, h2.y);
                ffma2(an[s], n2.x, h2.x); ffma2(an[s], n2.y, h2.y);
            }
        }
        float hn[4];
#pragma unroll
        for (int s = 0; s < 4; s++) {
            int n = nb + s;
            const float* xp = g_XP + ((size_t)n * 64 + tt) * NTOT + d * 768;
            float r  = sigm(xp[tid]       + upk_sum(ar[s]) + bh_r);
            float z  = sigm(xp[256 + tid] + upk_sum(az[s]) + bh_z);
            float ng = tanhf(xp[512 + tid] + r * (upk_sum(an[s]) + bh_n));
            hn[s] = (1.f - z) * ng + z * sh[s][tid];
        }
        __syncthreads();
#pragma unroll
        for (int s = 0; s < 4; s++) {
            sh[s][tid] = hn[s];
            g_F[((size_t)(nb + s) * 64 + tt) * 512 + d * 256 + tid] = hn[s];
        }
        __syncthreads();
    }
}

// ---------------- attention + softmax + Hc + cos/euc, one block per (k,b) ----------------
__global__ void __launch_bounds__(256) attn_kernel(
    const int* __restrict__ s_ln_arr, const int* __restrict__ q_ln_arr,
    float* __restrict__ d_out)
{
    extern __shared__ float sm[];
    float* ssc = sm;                 // [64][65] scores -> A
    float* sk  = sm + 64 * 65;       // [64][65] keys tile
    float* sq  = sk + 64 * 65;       // [64][65] F_Q tile
    float* shc = sq + 64 * 65;       // [64][520] Hc

    int kb = blockIdx.x;
    int b = kb & 31;
    int tid = threadIdx.x;
    int q_ln = q_ln_arr[b];
    int s_ln = s_ln_arr[kb];

    const float* keys = g_keys + (size_t)kb * 64 * 512;
    const float* FQ   = g_F + ((size_t)(160 + b) * 64) * 512;
    const float* FS   = g_F + ((size_t)kb * 64) * 512;

    int tx = tid & 15, ty = tid >> 4;
    float acc[4][4];
#pragma unroll
    for (int i = 0; i < 4; i++)
#pragma unroll
        for (int j = 0; j < 4; j++) acc[i][j] = 0.f;

    for (int g0 = 0; g0 < 512; g0 += 64) {
#pragma unroll
        for (int l = 0; l < 4; l++) {
            int idx = tid + l * 256;
            int row = idx >> 4;
            int col = (idx & 15) * 4;
            float4 v = *(const float4*)(keys + row * 512 + g0 + col);
            float* dk = sk + row * 65 + col;
            dk[0] = v.x; dk[1] = v.y; dk[2] = v.z; dk[3] = v.w;
            float4 w = *(const float4*)(FQ + row * 512 + g0 + col);
            float* dq = sq + row * 65 + col;
            dq[0] = w.x; dq[1] = w.y; dq[2] = w.z; dq[3] = w.w;
        }
        __syncthreads();
        for (int g = 0; g < 64; g++) {
            float a[4], bq[4];
#pragma unroll
            for (int i = 0; i < 4; i++) a[i]  = sk[(ty * 4 + i) * 65 + g];
#pragma unroll
            for (int j = 0; j < 4; j++) bq[j] = sq[(tx * 4 + j) * 65 + g];
#pragma unroll
            for (int i = 0; i < 4; i++)
#pragma unroll
                for (int j = 0; j < 4; j++) acc[i][j] += a[i] * bq[j];
        }
        __syncthreads();
    }
#pragma unroll
    for (int i = 0; i < 4; i++)
#pragma unroll
        for (int j = 0; j < 4; j++) {
            int s = ty * 4 + i, q = tx * 4 + j;
            ssc[s * 65 + q] = (q < q_ln) ? acc[i][j] : -INFINITY;
        }
    __syncthreads();

    int warp = tid >> 5, lane = tid & 31;
    for (int si = 0; si < 8; si++) {
        int s = warp * 8 + si;
        float v0 = ssc[s * 65 + lane];
        float v1 = ssc[s * 65 + 32 + lane];
        float mx = fmaxf(v0, v1);
#pragma unroll
        for (int o = 16; o > 0; o >>= 1) mx = fmaxf(mx, __shfl_xor_sync(~0u, mx, o));
        float e0 = expf(v0 - mx), e1 = expf(v1 - mx);
        float su = e0 + e1;
#pragma unroll
        for (int o = 16; o > 0; o >>= 1) su += __shfl_xor_sync(~0u, su, o);
        float sc = (s < s_ln) ? (1.f / su) : 0.f;
        ssc[s * 65 + lane] = e0 * sc;
        ssc[s * 65 + 32 + lane] = e1 * sc;
    }
    __syncthreads();

    if (kb == NS - 1) {
        for (int i = tid; i < 4096; i += 256)
            d_out[i] = ssc[(i >> 6) * 65 + (i & 63)];
    }

    int hcol = tid & 63;
    int qgrp = tid >> 6;
#pragma unroll
    for (int pass = 0; pass < 2; pass++) {
        int qb = qgrp * 8 + pass * 32;
        float hc[8][8];
#pragma unroll
        for (int qi = 0; qi < 8; qi++)
#pragma unroll
            for (int hj = 0; hj < 8; hj++) hc[qi][hj] = 0.f;
        for (int s = 0; s < 64; s++) {
            float4 f0 = *(const float4*)(FS + s * 512 + hcol * 8);
            float4 f1 = *(const float4*)(FS + s * 512 + hcol * 8 + 4);
#pragma unroll
            for (int qi = 0; qi < 8; qi++) {
                float a = ssc[s * 65 + qb + qi];
                hc[qi][0] += a * f0.x; hc[qi][1] += a * f0.y;
                hc[qi][2] += a * f0.z; hc[qi][3] += a * f0.w;
                hc[qi][4] += a * f1.x; hc[qi][5] += a * f1.y;
                hc[qi][6] += a * f1.z; hc[qi][7] += a * f1.w;
            }
        }
#pragma unroll
        for (int qi = 0; qi < 8; qi++) {
            float* dst = shc + (qb + qi) * 520 + hcol * 8;
#pragma unroll
            for (int hj = 0; hj < 8; hj++) dst[hj] = hc[qi][hj];
        }
    }
    __syncthreads();

    for (int qi = 0; qi < 8; qi++) {
        int q = warp + qi * 8;
        float dot = 0.f, nq = 0.f, nh = 0.f, ee = 0.f;
        for (int c = 0; c < 16; c++) {
            int h = lane + c * 32;
            float fq = FQ[q * 512 + h];
            float hv = shc[q * 520 + h];
            dot += fq * hv; nq += fq * fq; nh += hv * hv;
            float dd = fq - hv; ee += dd * dd;
        }
#pragma unroll
        for (int o = 16; o > 0; o >>= 1) {
            dot += __shfl_xor_sync(~0u, dot, o);
            nq  += __shfl_xor_sync(~0u, nq,  o);
            nh  += __shfl_xor_sync(~0u, nh,  o);
            ee  += __shfl_xor_sync(~0u, ee,  o);
        }
        if (lane == 0) {
            float cosv = dot / fmaxf(sqrtf(nq) * sqrtf(nh), 1e-6f);
            float eucv = sqrtf(ee);
            float msk = (q < q_ln) ? 1.f : 0.f;
            g_diff[((size_t)kb * 64 + q) * 2 + 0] = cosv * msk;
            g_diff[((size_t)kb * 64 + q) * 2 + 1] = eucv * msk;
        }
    }
}

// ---------------- dml GRU over diff + FC head: 40 blocks x 4 sequences ----------------
__global__ void __launch_bounds__(256) dml_kernel(
    const float* __restrict__ Wih, const float* __restrict__ Whh,
    const float* __restrict__ bih, const float* __restrict__ bhh,
    const float* __restrict__ fcW, const float* __restrict__ fcb,
    float* __restrict__ d_out)
{
    __shared__ __align__(16) float sh[4][256];
    __shared__ float red[256];
    int tid = threadIdx.x;
    int nb = blockIdx.x * 4;

#pragma unroll
    for (int s = 0; s < 4; s++) sh[s][tid] = 0.f;
    __syncthreads();

    float wi_r0 = Wih[tid * 2],         wi_r1 = Wih[tid * 2 + 1];
    float wi_z0 = Wih[(256 + tid) * 2], wi_z1 = Wih[(256 + tid) * 2 + 1];
    float wi_n0 = Wih[(512 + tid) * 2], wi_n1 = Wih[(512 + tid) * 2 + 1];
    float bi_r = bih[tid], bi_z = bih[256 + tid], bi_n = bih[512 + tid];
    float bh_r = bhh[tid], bh_z = bhh[256 + tid], bh_n = bhh[512 + tid];
    const float* wr = Whh + (size_t)tid * 256;
    const float* wz = Whh + (size_t)(256 + tid) * 256;
    const float* wn = Whh + (size_t)(512 + tid) * 256;

    for (int t = 0; t < 64; t++) {
        uint64_t ar[4] = {0,0,0,0}, az[4] = {0,0,0,0}, an[4] = {0,0,0,0};
        for (int i = 0; i < 256; i += 4) {
            ulonglong2 r2 = *(const ulonglong2*)(wr + i);
            ulonglong2 z2 = *(const ulonglong2*)(wz + i);
            ulonglong2 n2 = *(const ulonglong2*)(wn + i);
#pragma unroll
            for (int s = 0; s < 4; s++) {
                ulonglong2 h2 = *(const ulonglong2*)(&sh[s][i]);
                ffma2(ar[s], r2.x, h2.x); ffma2(ar[s], r2.y, h2.y);
                ffma2(az[s], z2.x, h2.x); ffma2(az[s], z2.y, h2.y);
                ffma2(an[s], n2.x, h2.x); ffma2(an[s], n2.y, h2.y);
            }
        }
        float hn[4];
#pragma unroll
        for (int s = 0; s < 4; s++) {
            int n = nb + s;
            float d0 = g_diff[((size_t)n * 64 + t) * 2 + 0];
            float d1 = g_diff[((size_t)n * 64 + t) * 2 + 1];
            float xr = wi_r0 * d0 + wi_r1 * d1 + bi_r;
            float xz = wi_z0 * d0 + wi_z1 * d1 + bi_z;
            float xn = wi_n0 * d0 + wi_n1 * d1 + bi_n;
            float r  = sigm(xr + upk_sum(ar[s]) + bh_r);
            float z  = sigm(xz + upk_sum(az[s]) + bh_z);
            float ng = tanhf(xn + r * (upk_sum(an[s]) + bh_n));
            hn[s] = (1.f - z) * ng + z * sh[s][tid];
        }
        __syncthreads();
#pragma unroll
        for (int s = 0; s < 4; s++) sh[s][tid] = hn[s];
        __syncthreads();
    }

    float fw = fcW[tid];
    for (int s = 0; s < 4; s++) {
        int n = nb + s;
        red[tid] = fw * sh[s][tid];
        __syncthreads();
        for (int off = 128; off > 0; off >>= 1) {
            if (tid < off) red[tid] += red[tid + off];
            __syncthreads();
        }
        if (tid == 0)
            d_out[4096 + n] = sigm(red[0] + fcb[0]);
        __syncthreads();
    }
}

// ---------------- launcher ----------------
extern "C" void kernel_launch(void* const* d_in, const int* in_sizes, int n_in,
                              void* d_out, int out_size)
{
    const float* feats_S  = (const float*)d_in[0];
    const float* feats_Q  = (const float*)d_in[1];
    const float* Wih_f    = (const float*)d_in[2];
    const float* Whh_f    = (const float*)d_in[3];
    const float* bih_f    = (const float*)d_in[4];
    const float* bhh_f    = (const float*)d_in[5];
    const float* Wih_b    = (const float*)d_in[6];
    const float* Whh_b    = (const float*)d_in[7];
    const float* bih_b    = (const float*)d_in[8];
    const float* bhh_b    = (const float*)d_in[9];
    const float* W_attn   = (const float*)d_in[10];
    const float* attn_b   = (const float*)d_in[11];
    const float* dml_Wih  = (const float*)d_in[12];
    const float* dml_Whh  = (const float*)d_in[13];
    const float* dml_bih  = (const float*)d_in[14];
    const float* dml_bhh  = (const float*)d_in[15];
    const float* fc_W     = (const float*)d_in[16];
    const float* fc_b     = (const float*)d_in[17];
    const int*   s_ln     = (const int*)d_in[18];
    const int*   q_ln     = (const int*)d_in[19];
    float* out = (float*)d_out;

    __nv_bfloat16 *abf, *bbf, *fbf, *wabf;
    float* fptr;
    cudaGetSymbolAddress((void**)&abf, g_Abf);
    cudaGetSymbolAddress((void**)&bbf, g_Bbf);
    cudaGetSymbolAddress((void**)&fbf, g_Fbf);
    cudaGetSymbolAddress((void**)&wabf, g_Wabf);
    cudaGetSymbolAddress((void**)&fptr, g_F);

    // 0) fp32 -> bf16 hi/lo split (3 launches; gemm_mma stays at ncu slot #4)
    convert_split<<<40960, 256>>>(feats_S, abf, abf + AELEMS);
    convert_split<<<8192, 256>>>(feats_Q, abf + (size_t)10240 * DIN,
                                 abf + AELEMS + (size_t)10240 * DIN);
    convert_w<<<6144, 256>>>(Wih_f, Wih_b, bbf, bbf + BELEMS);

    // 1) input projections via bf16 superchunk mma.sync
    cudaFuncSetAttribute(gemm_mma, cudaFuncAttributeMaxDynamicSharedMemorySize, GMM_SMEM);
    gemm_mma<<<dim3(12, 96), 256, GMM_SMEM>>>(bih_f, bih_b);

    // 2) GRU recurrence: 24 seq-groups x 2 directions, 4 seqs each
    bigru_scan<<<96, 256>>>(Whh_f, bhh_f, Whh_b, bhh_b);

    // 3) keys = W_attn(F_S) + bias via bf16 mma (convert F_S + W_attn first)
    convert_split<<<5120, 256>>>(fptr, fbf, fbf + FAEL);
    convert_split<<<256, 256>>>(W_attn, wabf, wabf + WAEL);
    cudaFuncSetAttribute(gemm_keys_mma, cudaFuncAttributeMaxDynamicSharedMemorySize, KEYS_SMEM);
    gemm_keys_mma<<<dim3(4, 80), 256, KEYS_SMEM>>>(attn_b);

    // 4) scores -> softmax -> A -> Hc -> (cos,euc)
    cudaFuncSetAttribute(attn_kernel, cudaFuncAttributeMaxDynamicSharedMemorySize, ATTN_SMEM);
    attn_kernel<<<160, 256, ATTN_SMEM>>>(s_ln, q_ln, out);

    // 5) dml GRU over (cos,euc) + sigmoid(FC)
    dml_kernel<<<40, 256>>>(dml_Wih, dml_Whh, dml_bih, dml_bhh, fc_W, fc_b, out);
}